// round 7
// baseline (speedup 1.0000x reference)
#include <cuda_runtime.h>
#include <cuda_bf16.h>
#include <cfloat>
#include <climits>
#include <cstdint>

// ---------------- problem constants ----------------
#define NQ    2048
#define NK    65536
#define DIM   256
#define TOPK  32

// kernel-1 tiling
#define QT     128               // queries per CTA
#define NQT    (NQ / QT)         // 16
#define NSL    64                // key slices
#define SLKEYS (NK / NSL)        // 1024 keys per slice
#define TN     64                // keys per tile (double-buffered)
#define NTILE  (SLKEYS / TN)     // 16
#define KPQ    12                // candidates kept per (query, slice)
#define KPQS   13
#define NCAND  (NSL * KPQ)       // 768 per query
#define TARGET 40                // approx top-N threshold for rescore
#define CAP    160               // collected-candidate buffer

// kernel-1 smem layout (bytes)
#define BS_BUF 32768             // 64 keys x 512 B packed (swizzled)
#define SS_OFF 65536
#define SROW   66
#define TV_OFF (SS_OFF + QT * SROW * 4)       // 99328
#define TI_OFF (TV_OFF + QT * KPQS * 4)       // 105984
#define SMEM1  (TI_OFF + QT * KPQS * 4)       // 112640

// ---------------- device scratch (globals, no allocs) ----------------
__device__ __nv_bfloat16 g_kb[(size_t)NK * DIM];   // 32 MB bf16 keys
__device__ float g_pv[(size_t)NQ * NCAND];         // 6 MB
__device__ int   g_pi[(size_t)NQ * NCAND];         // 6 MB

// ---------------- PTX helpers (base sm_103 ISA only) ----------------
__device__ __forceinline__ uint32_t smem_u32(const void* p) {
    uint32_t a;
    asm("{ .reg .u64 t; cvta.to.shared.u64 t, %1; cvt.u32.u64 %0, t; }" : "=r"(a) : "l"(p));
    return a;
}

#define LDSM4(r, addr) \
    asm volatile("ldmatrix.sync.aligned.m8n8.x4.shared.b16 {%0,%1,%2,%3}, [%4];" \
        : "=r"((r)[0]), "=r"((r)[1]), "=r"((r)[2]), "=r"((r)[3]) : "r"(addr))

#define MMA16816(d, A, b0, b1) \
    asm volatile("mma.sync.aligned.m16n8k16.row.col.f32.bf16.bf16.f32 " \
        "{%0,%1,%2,%3}, {%4,%5,%6,%7}, {%8,%9}, {%0,%1,%2,%3};" \
        : "+f"((d)[0]), "+f"((d)[1]), "+f"((d)[2]), "+f"((d)[3]) \
        : "r"((A)[0]), "r"((A)[1]), "r"((A)[2]), "r"((A)[3]), "r"(b0), "r"(b1))

#define CP_ASYNC16(dst, src) \
    asm volatile("cp.async.cg.shared.global [%0], [%1], 16;" :: "r"(dst), "l"(src))
#define CP_COMMIT() asm volatile("cp.async.commit_group;" ::: "memory")
#define CP_WAIT1()  asm volatile("cp.async.wait_group 1;" ::: "memory")
#define CP_WAIT0()  asm volatile("cp.async.wait_group 0;" ::: "memory")

// monotonic float -> uint mapping (descending value = descending u)
__device__ __forceinline__ uint32_t mono(float f) {
    uint32_t u = __float_as_uint(f);
    return (u & 0x80000000u) ? ~u : (u | 0x80000000u);
}

// ---------------- kernel 0: keys fp32 -> bf16 ----------------
__global__ __launch_bounds__(256)
void convert_keys_kernel(const float* __restrict__ keys) {
    size_t idx = ((size_t)blockIdx.x * 256 + threadIdx.x) * 8;
    float4 a = *(const float4*)(keys + idx);
    float4 b = *(const float4*)(keys + idx + 4);
    __nv_bfloat162 p0 = __float22bfloat162_rn(make_float2(a.x, a.y));
    __nv_bfloat162 p1 = __float22bfloat162_rn(make_float2(a.z, a.w));
    __nv_bfloat162 p2 = __float22bfloat162_rn(make_float2(b.x, b.y));
    __nv_bfloat162 p3 = __float22bfloat162_rn(make_float2(b.z, b.w));
    uint4 o;
    o.x = *(uint32_t*)&p0; o.y = *(uint32_t*)&p1;
    o.z = *(uint32_t*)&p2; o.w = *(uint32_t*)&p3;
    *(uint4*)(g_kb + idx) = o;
}

// ---------------- kernel 1: HMMA scores, cp.async pipelined ---------------
__device__ __forceinline__ void prefetch_tile(uint32_t bs, int slice, int t, int tid) {
    const char* kb = (const char*)(g_kb + ((size_t)slice * SLKEYS + (size_t)t * TN) * DIM);
    uint32_t dstbase = bs + (uint32_t)(t & 1) * BS_BUF;
    #pragma unroll
    for (int j = 0; j < 16; ++j) {
        int seg = tid + 128 * j;
        int row = seg >> 5;      // key 0..63
        int ch  = seg & 31;      // 16B chunk 0..31
        uint32_t dst = dstbase + (uint32_t)row * 512 + ((uint32_t)(ch ^ (row & 7)) << 4);
        CP_ASYNC16(dst, kb + row * 512 + ch * 16);
    }
}

__global__ __launch_bounds__(128, 2)
void score_topk_kernel(const float* __restrict__ query) {
    extern __shared__ char smem[];
    uint32_t sb = smem_u32(smem);
    float* Ss = (float*)(smem + SS_OFF);
    float* Tv = (float*)(smem + TV_OFF);
    int*   Ti = (int*)(smem + TI_OFF);

    const int tid  = threadIdx.x;
    const int wid  = tid >> 5;
    const int lane = tid & 31;
    const int slice = blockIdx.x;
    const int qb    = blockIdx.y * QT;

    // ---- persistent A fragments (fp32 -> bf16 cvt in flight) ----
    uint32_t a[2][16][4];
    {
        const int tq = lane >> 2;
        const int tk = (lane & 3) * 2;
        #pragma unroll
        for (int mb = 0; mb < 2; ++mb) {
            const float* b0 = query + (size_t)(qb + wid * 32 + mb * 16 + tq) * DIM;
            const float* b1 = b0 + 8 * DIM;
            #pragma unroll
            for (int ks = 0; ks < 16; ++ks) {
                float2 f0 = *(const float2*)(b0 + ks * 16 + tk);
                float2 f1 = *(const float2*)(b1 + ks * 16 + tk);
                float2 f2 = *(const float2*)(b0 + ks * 16 + tk + 8);
                float2 f3 = *(const float2*)(b1 + ks * 16 + tk + 8);
                __nv_bfloat162 p0 = __float22bfloat162_rn(f0);
                __nv_bfloat162 p1 = __float22bfloat162_rn(f1);
                __nv_bfloat162 p2 = __float22bfloat162_rn(f2);
                __nv_bfloat162 p3 = __float22bfloat162_rn(f3);
                a[mb][ks][0] = *(uint32_t*)&p0;
                a[mb][ks][1] = *(uint32_t*)&p1;
                a[mb][ks][2] = *(uint32_t*)&p2;
                a[mb][ks][3] = *(uint32_t*)&p3;
            }
        }
    }

    // ---- top-k state (thread tid owns query tid) ----
    float* Tr = Tv + tid * KPQS;
    int*   Ir = Ti + tid * KPQS;
    #pragma unroll
    for (int j = 0; j < KPQ; ++j) { Tr[j] = -FLT_MAX; Ir[j] = 0; }
    float minv = -FLT_MAX;
    int   minslot = 0;

    // ---- ldmatrix lane constants (non-trans x4, swizzled packed rows) ----
    const int key0 = ((lane >> 4) & 1) * 8 + (lane & 7);   // 0..15
    const int cbit = (lane >> 3) & 1;
    const int k7   = key0 & 7;           // invariant under +16/+32 key offsets
    const uint32_t rowA = (uint32_t)key0 * 512;

    const int sq0 = wid * 32 + (lane >> 2);
    const int sk0 = (lane & 3) * 2;

    // ---- pipeline prologue ----
    prefetch_tile(sb, slice, 0, tid); CP_COMMIT();
    prefetch_tile(sb, slice, 1, tid); CP_COMMIT();

    #pragma unroll 1
    for (int t = 0; t < NTILE; ++t) {
        if (t + 1 < NTILE) { CP_WAIT1(); } else { CP_WAIT0(); }
        __syncthreads();
        const uint32_t buf = sb + (uint32_t)(t & 1) * BS_BUF;

        #pragma unroll
        for (int h = 0; h < 2; ++h) {
            float c[2][4][4];
            #pragma unroll
            for (int mb = 0; mb < 2; ++mb)
                #pragma unroll
                for (int nt = 0; nt < 4; ++nt)
                    #pragma unroll
                    for (int e = 0; e < 4; ++e) c[mb][nt][e] = 0.0f;

            const uint32_t base0 = buf + rowA + (uint32_t)(h * 32) * 512;
            const uint32_t base1 = base0 + 16u * 512;
            #pragma unroll
            for (int ks = 0; ks < 16; ++ks) {
                uint32_t off = (uint32_t)(((2 * ks + cbit) ^ k7) << 4);
                uint32_t b[8];
                LDSM4(b,     base0 + off);   // keys h*32+0..15  -> nt0, nt1
                LDSM4(b + 4, base1 + off);   // keys h*32+16..31 -> nt2, nt3
                #pragma unroll
                for (int mb = 0; mb < 2; ++mb) {
                    MMA16816(c[mb][0], a[mb][ks], b[0], b[1]);
                    MMA16816(c[mb][1], a[mb][ks], b[2], b[3]);
                    MMA16816(c[mb][2], a[mb][ks], b[4], b[5]);
                    MMA16816(c[mb][3], a[mb][ks], b[6], b[7]);
                }
            }
            // D frags -> Ss cols [h*32, h*32+32)
            #pragma unroll
            for (int mb = 0; mb < 2; ++mb) {
                #pragma unroll
                for (int nt = 0; nt < 4; ++nt) {
                    int qq = sq0 + mb * 16;
                    int kk = h * 32 + nt * 8 + sk0;
                    *(float2*)&Ss[qq * SROW + kk]       = make_float2(c[mb][nt][0], c[mb][nt][1]);
                    *(float2*)&Ss[(qq + 8) * SROW + kk] = make_float2(c[mb][nt][2], c[mb][nt][3]);
                }
            }
        }
        __syncthreads();   // all warps done reading buf
        if (t + 2 < NTILE) { prefetch_tile(sb, slice, t + 2, tid); CP_COMMIT(); }

        // ---- streaming top-12 over this tile's 64 scores (overlaps cp.async) ----
        __syncwarp();
        {
            const float* srow = Ss + tid * SROW;
            const int base = slice * SLKEYS + t * TN;
            #pragma unroll
            for (int k = 0; k < TN; ++k) {
                float s = srow[k];
                if (s > minv) {
                    Tr[minslot] = s; Ir[minslot] = base + k;
                    float m = Tr[0]; int ms = 0;
                    #pragma unroll
                    for (int j = 1; j < KPQ; ++j) {
                        float u = Tr[j];
                        if (u < m) { m = u; ms = j; }
                    }
                    minv = m; minslot = ms;
                }
            }
        }
    }

    // ---- write per-slice candidates ----
    const size_t qg = (size_t)qb + tid;
    #pragma unroll
    for (int j = 0; j < KPQ; ++j) {
        g_pv[qg * NCAND + slice * KPQ + j] = Tr[j];
        g_pi[qg * NCAND + slice * KPQ + j] = Ir[j];
    }
}

// ---------------- kernel 2: histogram select + exact rescore + gather -----
__device__ __forceinline__ void amax3(float& v, int& i, int& p, float v2, int i2, int p2) {
    if (v2 > v || (v2 == v && i2 < i)) { v = v2; i = i2; p = p2; }
}

__global__ __launch_bounds__(256)
void merge_kernel(const float* __restrict__ query,
                  const float* __restrict__ keys,
                  const float* __restrict__ vals,
                  float* __restrict__ out) {
    __shared__ float cv[NCAND];
    __shared__ int   ci[NCAND];
    __shared__ int   hist[4096];
    __shared__ int   coarse[256];
    __shared__ int   thrBin, collN;
    __shared__ int   ridx[CAP];
    __shared__ float rs[CAP];
    __shared__ float qrow[DIM];
    __shared__ float selv[TOPK];
    __shared__ int   seli[TOPK];
    __shared__ float wts[TOPK];

    const int q = blockIdx.x;
    const int tid = threadIdx.x;
    const int w = tid >> 5, lane = tid & 31;

    for (int i = tid; i < NCAND; i += 256) {
        cv[i] = g_pv[(size_t)q * NCAND + i];
        ci[i] = g_pi[(size_t)q * NCAND + i];
    }
    qrow[tid] = query[(size_t)q * DIM + tid];
    #pragma unroll
    for (int j = 0; j < 16; ++j) hist[tid * 16 + j] = 0;
    if (tid == 0) collN = 0;
    __syncthreads();

    // --- histogram of monotonic-mapped bf16 scores (top 12 bits) ---
    for (int i = tid; i < NCAND; i += 256)
        atomicAdd(&hist[mono(cv[i]) >> 20], 1);
    __syncthreads();

    { int s = 0;
      #pragma unroll
      for (int j = 0; j < 16; ++j) s += hist[tid * 16 + j];
      coarse[tid] = s; }
    __syncthreads();

    // --- find threshold bin: smallest value bin s.t. count(>= bin) >= TARGET ---
    if (tid == 0) {
        int acc = 0, cb = 255;
        for (; cb >= 0; --cb) { acc += coarse[cb]; if (acc >= TARGET) break; }
        int acc2 = acc - coarse[cb];
        int fb = cb * 16 + 15;
        for (; fb > cb * 16; --fb) { acc2 += hist[fb]; if (acc2 >= TARGET) break; }
        if (acc2 < TARGET) fb = cb * 16;
        thrBin = fb;
    }
    __syncthreads();

    // --- collect all candidates at/above threshold bin ---
    const int tb = thrBin;
    for (int i = tid; i < NCAND; i += 256) {
        if ((int)(mono(cv[i]) >> 20) >= tb) {
            int p = atomicAdd(&collN, 1);
            if (p < CAP) ridx[p] = ci[i];
        }
    }
    __syncthreads();
    const int M = (collN < CAP) ? collN : CAP;
    for (int i = tid; i < CAP; i += 256)
        if (i >= M) { rs[i] = -FLT_MAX; ridx[i] = INT_MAX; }
    __syncthreads();

    // --- exact fp32 rescore of collected (one per warp, round-robin) ---
    for (int j = w; j < M; j += 8) {
        const float* kr = keys + (size_t)ridx[j] * DIM;
        float acc = 0.0f;
        #pragma unroll
        for (int d = 0; d < DIM / 32; ++d)
            acc = fmaf(qrow[lane + d * 32], kr[lane + d * 32], acc);
        #pragma unroll
        for (int o = 16; o > 0; o >>= 1) acc += __shfl_xor_sync(0xffffffffu, acc, o);
        if (lane == 0) rs[j] = acc;
    }
    __syncthreads();

    // --- exact top-32 over collected (warp 0; jax tie-break lower index) ---
    if (w == 0) {
        for (int it = 0; it < TOPK; ++it) {
            float bv = -FLT_MAX; int bi = INT_MAX, bp = 0;
            #pragma unroll
            for (int r = 0; r < CAP / 32; ++r) {
                int i = lane + r * 32;
                amax3(bv, bi, bp, rs[i], ridx[i], i);
            }
            #pragma unroll
            for (int o = 16; o > 0; o >>= 1) {
                float ov = __shfl_xor_sync(0xffffffffu, bv, o);
                int oi = __shfl_xor_sync(0xffffffffu, bi, o);
                int op = __shfl_xor_sync(0xffffffffu, bp, o);
                amax3(bv, bi, bp, ov, oi, op);
            }
            if (lane == 0) { selv[it] = bv; seli[it] = bi; rs[bp] = -FLT_MAX; }
            __syncwarp();
        }
        float s = selv[lane] * 0.0625f;   // D_MODEL^-0.5
        float m = s;
        #pragma unroll
        for (int o = 16; o > 0; o >>= 1) m = fmaxf(m, __shfl_xor_sync(0xffffffffu, m, o));
        float e = expf(s - m);
        float sum = e;
        #pragma unroll
        for (int o = 16; o > 0; o >>= 1) sum += __shfl_xor_sync(0xffffffffu, sum, o);
        wts[lane] = e / sum;
    }
    __syncthreads();

    // --- gather + weighted sum (thread = output dim) ---
    const int d = tid;
    float acc = 0.0f;
    #pragma unroll 8
    for (int j = 0; j < TOPK; ++j)
        acc += wts[j] * __ldg(vals + (size_t)seli[j] * DIM + d);
    out[(size_t)q * DIM + d] = acc;
}

// ---------------- host launch ----------------
extern "C" void kernel_launch(void* const* d_in, const int* in_sizes, int n_in,
                              void* d_out, int out_size) {
    const float* query = (const float*)d_in[0];   // [4,512,256]
    const float* keys  = (const float*)d_in[1];   // [65536,256]
    const float* vals  = (const float*)d_in[2];   // [65536,256]
    float* out = (float*)d_out;

    cudaFuncSetAttribute(score_topk_kernel,
                         cudaFuncAttributeMaxDynamicSharedMemorySize, SMEM1);

    convert_keys_kernel<<<(NK * DIM) / (256 * 8), 256>>>(keys);
    score_topk_kernel<<<dim3(NSL, NQT), 128, SMEM1>>>(query);
    merge_kernel<<<NQ, 256>>>(query, keys, vals, out);
}